// round 1
// baseline (speedup 1.0000x reference)
#include <cuda_runtime.h>
#include <math.h>

#define BATCH 16
#define COUT 64
#define RANK 4
#define EPSBN 1e-5f

// layer geometry
#define H1IN 128
#define W1IN 256
#define HO1  130
#define WO1  258
#define HO2  132
#define WO2  260
#define POH  44
#define POW  86

// scratch (static device arrays — no allocations allowed)
__device__ float g_h1[(size_t)BATCH * COUT * HO1 * WO1];   // ~137 MB
__device__ float g_h2[(size_t)BATCH * COUT * HO2 * WO2];   // ~140 MB
__device__ float g_stats[4 * COUT];                        // sum1,sq1,sum2,sq2
__device__ float g_st[4 * COUT];                           // s1,t1,s2,t2

__global__ void zero_stats_kernel() {
    int i = threadIdx.x;
    if (i < 4 * COUT) g_stats[i] = 0.f;
}

// Per-channel BN scale/shift from accumulated sums.
__global__ void finalize_stats_kernel(const float* __restrict__ sums,
                                      const float* __restrict__ gam,
                                      const float* __restrict__ bet,
                                      float* __restrict__ st, float N) {
    int c = threadIdx.x;
    if (c < COUT) {
        float mean = sums[c] / N;
        float var  = sums[COUT + c] / N - mean * mean;
        float s    = gam[c] * rsqrtf(var + EPSBN);
        st[c]         = s;
        st[COUT + c]  = bet[c] - mean * s;
    }
}

// LRLC conv: y[b,o,h,w] = sum_{ci,kh,kw} x[b,ci,h-2+kh,w-2+kw] * (sum_r cw[r,h,w]*w[r,o,ci,kh,kw]) + bias[o]
// One CTA: one output row h, 32 output cols, all 64 out channels, all 16 batch.
// Thread (tx, og): pixel (h, w0+tx), channels og*4..og*4+3, all 16 batch -> 64 accumulators.
// Weights folded with cw per k once, reused across 16 batch (25% fold overhead).
// FUSED: input is previous layer pre-BN output; apply relu(v*s[c]+t[c]) while staging.
template<int CIN, int HIN, int WIN, int HO, int WO, bool FUSED>
__global__ __launch_bounds__(512, 1)
void lrlc_conv_kernel(const float* __restrict__ xin,
                      const float* __restrict__ wgt,   // [r][o][ci][3][3]
                      const float* __restrict__ bias,
                      const float* __restrict__ ah,    // [r][HO]
                      const float* __restrict__ aw,    // [r][WO]
                      const float* __restrict__ st,    // s[64],t[64] (FUSED only)
                      float* __restrict__ yout,        // [b][o][HO][WO]
                      float* __restrict__ stats)       // sum[64], sumsq[64]
{
    extern __shared__ float sm[];
    float* wsm = sm;                    // [72 kl][64 o][4 r]  = 18432 floats
    float* xsm = sm + 72 * 64 * 4;      // [8 cl][3 kh][4 bg][34 col][4 b4] = 13056 floats

    const int tx   = threadIdx.x;       // 0..31  (w lane)
    const int og   = threadIdx.y;       // 0..15  (channel group)
    const int tid  = og * 32 + tx;
    const int lane = tx;
    const int wid  = og;                // warp index (blockDim.x == 32)

    const int h  = blockIdx.y;
    const int w0 = blockIdx.x * 32;
    const int wq = w0 + tx;
    const bool wvalid = (wq < WO);
    const int wc = wvalid ? wq : (WO - 1);

    // combining weights (softmax over rank)
    float lg[RANK];
#pragma unroll
    for (int r = 0; r < RANK; ++r)
        lg[r] = ah[r * HO + h] + aw[r * WO + wc];
    float mx = fmaxf(fmaxf(lg[0], lg[1]), fmaxf(lg[2], lg[3]));
    float cw[RANK];
    float esum = 0.f;
#pragma unroll
    for (int r = 0; r < RANK; ++r) { cw[r] = expf(lg[r] - mx); esum += cw[r]; }
    float einv = 1.f / esum;
#pragma unroll
    for (int r = 0; r < RANK; ++r) cw[r] *= einv;

    float acc[64];
#pragma unroll
    for (int i = 0; i < 64; ++i) acc[i] = 0.f;

    const int obase = og * 4;

    for (int cc = 0; cc < CIN / 8; ++cc) {
        __syncthreads();

        // ---- stage weights: wsm[(kl*64+o)*4 + r], vectorized STS.128, o innermost across lanes
#pragma unroll
        for (int mIt = 0; mIt < 9; ++mIt) {
            int p  = tid + mIt * 512;      // 72*64 = 4608 = 9*512
            int o  = p & 63;
            int kl = p >> 6;
            float4 wv;
            wv.x = wgt[(0 * COUT + o) * (CIN * 9) + cc * 72 + kl];
            wv.y = wgt[(1 * COUT + o) * (CIN * 9) + cc * 72 + kl];
            wv.z = wgt[(2 * COUT + o) * (CIN * 9) + cc * 72 + kl];
            wv.w = wgt[(3 * COUT + o) * (CIN * 9) + cc * 72 + kl];
            *(float4*)&wsm[(kl * 64 + o) * 4] = wv;
        }

        // ---- stage x: xsm[(((cl*3+kh)*4+bg)*34+col)*4 + b4]; one warp per (b, cl, kh) strip
        for (int s = wid; s < 384; s += 16) {
            int b   = s & 15;
            int rc  = s >> 4;          // 0..23
            int cl  = rc / 3;
            int kh  = rc - cl * 3;
            int row = h - 2 + kh;
            int cin = cc * 8 + cl;
            const float* src = xin + ((size_t)(b * CIN + cin) * HIN + row) * WIN;
            float sc = 0.f, tc = 0.f;
            if (FUSED) { sc = st[cin]; tc = st[COUT + cin]; }
            int base = (((cl * 3 + kh) * 4 + (b >> 2)) * 34) * 4 + (b & 3);
            bool rowok = (row >= 0) && (row < HIN);

            int col_l = lane;
            {
                int col = w0 - 2 + col_l;
                bool ok = rowok && (col >= 0) && (col < WIN);
                float v = ok ? src[col] : 0.f;
                if (FUSED) v = ok ? fmaxf(v * sc + tc, 0.f) : 0.f;
                xsm[base + col_l * 4] = v;
            }
            if (lane < 2) {
                int col_l2 = lane + 32;
                int col = w0 - 2 + col_l2;
                bool ok = rowok && (col >= 0) && (col < WIN);
                float v = ok ? src[col] : 0.f;
                if (FUSED) v = ok ? fmaxf(v * sc + tc, 0.f) : 0.f;
                xsm[base + col_l2 * 4] = v;
            }
        }

        __syncthreads();

        // ---- main compute
#pragma unroll 1
        for (int cl = 0; cl < 8; ++cl) {
#pragma unroll
            for (int kh = 0; kh < 3; ++kh) {
                const float* xrow = &xsm[(((cl * 3 + kh) * 4) * 34) * 4];
#pragma unroll
                for (int kw = 0; kw < 3; ++kw) {
                    int kl = cl * 9 + kh * 3 + kw;
                    const float4* wp = (const float4*)&wsm[(kl * 64 + obase) * 4];
                    float weff[4];
#pragma unroll
                    for (int j = 0; j < 4; ++j) {
                        float4 wv = wp[j];
                        weff[j] = cw[0] * wv.x + cw[1] * wv.y + cw[2] * wv.z + cw[3] * wv.w;
                    }
#pragma unroll
                    for (int bg = 0; bg < 4; ++bg) {
                        float4 xv = *(const float4*)&xrow[(bg * 34 + tx + kw) * 4];
#pragma unroll
                        for (int j = 0; j < 4; ++j) {
                            acc[j * 16 + bg * 4 + 0] = fmaf(weff[j], xv.x, acc[j * 16 + bg * 4 + 0]);
                            acc[j * 16 + bg * 4 + 1] = fmaf(weff[j], xv.y, acc[j * 16 + bg * 4 + 1]);
                            acc[j * 16 + bg * 4 + 2] = fmaf(weff[j], xv.z, acc[j * 16 + bg * 4 + 2]);
                            acc[j * 16 + bg * 4 + 3] = fmaf(weff[j], xv.w, acc[j * 16 + bg * 4 + 3]);
                        }
                    }
                }
            }
        }
    }

    // ---- epilogue: bias, store, BN-stat accumulation
#pragma unroll
    for (int j = 0; j < 4; ++j) {
        int o = obase + j;
        float bia = bias[o];
        float s0 = 0.f, s1 = 0.f;
#pragma unroll
        for (int b = 0; b < 16; ++b) {
            float v = acc[j * 16 + b] + bia;
            if (wvalid)
                yout[((size_t)(b * COUT + o) * HO + h) * WO + wq] = v;
            float vs = wvalid ? v : 0.f;
            s0 += vs;
            s1 += vs * vs;
        }
#pragma unroll
        for (int off = 16; off > 0; off >>= 1) {
            s0 += __shfl_xor_sync(0xffffffffu, s0, off);
            s1 += __shfl_xor_sync(0xffffffffu, s1, off);
        }
        if (lane == 0) {
            atomicAdd(&stats[o], s0);
            atomicAdd(&stats[COUT + o], s1);
        }
    }
}

// BN + ReLU + 3x3/3 maxpool (all candidates >= 0 after relu, so init 0 is exact)
__global__ void bn_relu_pool_kernel(const float* __restrict__ h2,
                                    const float* __restrict__ st,
                                    float* __restrict__ out) {
    int idx = blockIdx.x * blockDim.x + threadIdx.x;
    const int total = BATCH * COUT * POH * POW;
    if (idx >= total) return;
    int ow = idx % POW;
    int t  = idx / POW;
    int oh = t % POH;  t /= POH;
    int c  = t % COUT;
    int b  = t / COUT;
    float s  = st[c];
    float tt = st[COUT + c];
    const float* p = h2 + ((size_t)(b * COUT + c) * HO2 + oh * 3) * WO2 + ow * 3;
    float v = 0.f;
#pragma unroll
    for (int kh = 0; kh < 3; ++kh)
#pragma unroll
        for (int kw = 0; kw < 3; ++kw) {
            float u = fmaxf(p[kh * WO2 + kw] * s + tt, 0.f);
            v = fmaxf(v, u);
        }
    out[idx] = v;
}

extern "C" void kernel_launch(void* const* d_in, const int* in_sizes, int n_in,
                              void* d_out, int out_size) {
    const float* x   = (const float*)d_in[0];
    const float* w1  = (const float*)d_in[1];
    const float* b1  = (const float*)d_in[2];
    const float* a1h = (const float*)d_in[3];
    const float* a1w = (const float*)d_in[4];
    const float* g1  = (const float*)d_in[5];
    const float* be1 = (const float*)d_in[6];
    const float* w2  = (const float*)d_in[7];
    const float* b2  = (const float*)d_in[8];
    const float* a2h = (const float*)d_in[9];
    const float* a2w = (const float*)d_in[10];
    const float* g2  = (const float*)d_in[11];
    const float* be2 = (const float*)d_in[12];

    float *h1, *h2, *stats, *st;
    cudaGetSymbolAddress((void**)&h1, g_h1);
    cudaGetSymbolAddress((void**)&h2, g_h2);
    cudaGetSymbolAddress((void**)&stats, g_stats);
    cudaGetSymbolAddress((void**)&st, g_st);

    const size_t smem = (size_t)(72 * 64 * 4 + 8 * 3 * 4 * 34 * 4) * sizeof(float); // 125,952 B
    cudaFuncSetAttribute(lrlc_conv_kernel<32, 128, 256, 130, 258, false>,
                         cudaFuncAttributeMaxDynamicSharedMemorySize, (int)smem);
    cudaFuncSetAttribute(lrlc_conv_kernel<64, 130, 258, 132, 260, true>,
                         cudaFuncAttributeMaxDynamicSharedMemorySize, (int)smem);

    zero_stats_kernel<<<1, 256>>>();

    dim3 blk(32, 16);
    // layer 1: 258 cols -> 9 tiles of 32
    lrlc_conv_kernel<32, 128, 256, 130, 258, false>
        <<<dim3(9, 130), blk, smem>>>(x, w1, b1, a1h, a1w, nullptr, h1, stats);
    finalize_stats_kernel<<<1, 64>>>(stats, g1, be1, st, (float)(BATCH * 130 * 258));

    // layer 2: 260 cols -> 9 tiles (input BN+ReLU fused during staging)
    lrlc_conv_kernel<64, 130, 258, 132, 260, true>
        <<<dim3(9, 132), blk, smem>>>(h1, w2, b2, a2h, a2w, st, h2, stats + 128);
    finalize_stats_kernel<<<1, 64>>>(stats + 128, g2, be2, st + 128, (float)(BATCH * 132 * 260));

    const int total = BATCH * COUT * POH * POW;
    bn_relu_pool_kernel<<<(total + 255) / 256, 256>>>(h2, st + 128, (float*)d_out);
}

// round 2
// speedup vs baseline: 1.0026x; 1.0026x over previous
#include <cuda_runtime.h>
#include <math.h>

#define BATCH 16
#define COUT 64
#define RANK 4
#define EPSBN 1e-5f

// layer geometry
#define H1IN 128
#define W1IN 256
#define HO1  130
#define WO1  258
#define HO2  132
#define WO2  260
#define POH  44
#define POW  86

// scratch (static device arrays — no allocations allowed)
__device__ float g_h1[(size_t)BATCH * COUT * HO1 * WO1];   // ~137 MB
__device__ float g_h2[(size_t)BATCH * COUT * HO2 * WO2];   // ~140 MB
__device__ float g_stats[4 * COUT];                        // sum1,sq1,sum2,sq2
__device__ float g_st[4 * COUT];                           // s1,t1,s2,t2

__global__ void zero_stats_kernel() {
    int i = threadIdx.x;
    if (i < 4 * COUT) g_stats[i] = 0.f;
}

// Per-channel BN scale/shift from accumulated sums.
__global__ void finalize_stats_kernel(const float* __restrict__ sums,
                                      const float* __restrict__ gam,
                                      const float* __restrict__ bet,
                                      float* __restrict__ st, float N) {
    int c = threadIdx.x;
    if (c < COUT) {
        float mean = sums[c] / N;
        float var  = sums[COUT + c] / N - mean * mean;
        float s    = gam[c] * rsqrtf(var + EPSBN);
        st[c]         = s;
        st[COUT + c]  = bet[c] - mean * s;
    }
}

// LRLC conv: y[b,o,h,w] = sum_{ci,kh,kw} x[b,ci,h-2+kh,w-2+kw] * (sum_r cw[r,h,w]*w[r,o,ci,kh,kw]) + bias[o]
// One CTA: one output row h, 32 output cols, all 64 out channels, all 16 batch.
// Thread (tx, og): pixel (h, w0+tx), channels og*4..og*4+3, all 16 batch -> 64 accumulators.
// Weights folded with cw per k once, reused across 16 batch (25% fold overhead).
// FUSED: input is previous layer pre-BN output; apply relu(v*s[c]+t[c]) while staging.
template<int CIN, int HIN, int WIN, int HO, int WO, bool FUSED>
__global__ __launch_bounds__(512, 1)
void lrlc_conv_kernel(const float* __restrict__ xin,
                      const float* __restrict__ wgt,   // [r][o][ci][3][3]
                      const float* __restrict__ bias,
                      const float* __restrict__ ah,    // [r][HO]
                      const float* __restrict__ aw,    // [r][WO]
                      const float* __restrict__ st,    // s[64],t[64] (FUSED only)
                      float* __restrict__ yout,        // [b][o][HO][WO]
                      float* __restrict__ stats)       // sum[64], sumsq[64]
{
    extern __shared__ float sm[];
    float* wsm = sm;                    // [72 kl][64 o][4 r]  = 18432 floats
    float* xsm = sm + 72 * 64 * 4;      // [8 cl][3 kh][4 bg][34 col][4 b4] = 13056 floats

    const int tx   = threadIdx.x;       // 0..31  (w lane)
    const int og   = threadIdx.y;       // 0..15  (channel group)
    const int tid  = og * 32 + tx;
    const int lane = tx;
    const int wid  = og;                // warp index (blockDim.x == 32)

    const int h  = blockIdx.y;
    const int w0 = blockIdx.x * 32;
    const int wq = w0 + tx;
    const bool wvalid = (wq < WO);
    const int wc = wvalid ? wq : (WO - 1);

    // combining weights (softmax over rank)
    float lg[RANK];
#pragma unroll
    for (int r = 0; r < RANK; ++r)
        lg[r] = ah[r * HO + h] + aw[r * WO + wc];
    float mx = fmaxf(fmaxf(lg[0], lg[1]), fmaxf(lg[2], lg[3]));
    float cw[RANK];
    float esum = 0.f;
#pragma unroll
    for (int r = 0; r < RANK; ++r) { cw[r] = expf(lg[r] - mx); esum += cw[r]; }
    float einv = 1.f / esum;
#pragma unroll
    for (int r = 0; r < RANK; ++r) cw[r] *= einv;

    float acc[64];
#pragma unroll
    for (int i = 0; i < 64; ++i) acc[i] = 0.f;

    const int obase = og * 4;

    for (int cc = 0; cc < CIN / 8; ++cc) {
        __syncthreads();

        // ---- stage weights: wsm[(kl*64+o)*4 + r], vectorized STS.128, o innermost across lanes
#pragma unroll
        for (int mIt = 0; mIt < 9; ++mIt) {
            int p  = tid + mIt * 512;      // 72*64 = 4608 = 9*512
            int o  = p & 63;
            int kl = p >> 6;
            float4 wv;
            wv.x = wgt[(0 * COUT + o) * (CIN * 9) + cc * 72 + kl];
            wv.y = wgt[(1 * COUT + o) * (CIN * 9) + cc * 72 + kl];
            wv.z = wgt[(2 * COUT + o) * (CIN * 9) + cc * 72 + kl];
            wv.w = wgt[(3 * COUT + o) * (CIN * 9) + cc * 72 + kl];
            *(float4*)&wsm[(kl * 64 + o) * 4] = wv;
        }

        // ---- stage x: xsm[(((cl*3+kh)*4+bg)*34+col)*4 + b4]; one warp per (b, cl, kh) strip
        for (int s = wid; s < 384; s += 16) {
            int b   = s & 15;
            int rc  = s >> 4;          // 0..23
            int cl  = rc / 3;
            int kh  = rc - cl * 3;
            int row = h - 2 + kh;
            int cin = cc * 8 + cl;
            const float* src = xin + ((size_t)(b * CIN + cin) * HIN + row) * WIN;
            float sc = 0.f, tc = 0.f;
            if (FUSED) { sc = st[cin]; tc = st[COUT + cin]; }
            int base = (((cl * 3 + kh) * 4 + (b >> 2)) * 34) * 4 + (b & 3);
            bool rowok = (row >= 0) && (row < HIN);

            int col_l = lane;
            {
                int col = w0 - 2 + col_l;
                bool ok = rowok && (col >= 0) && (col < WIN);
                float v = ok ? src[col] : 0.f;
                if (FUSED) v = ok ? fmaxf(v * sc + tc, 0.f) : 0.f;
                xsm[base + col_l * 4] = v;
            }
            if (lane < 2) {
                int col_l2 = lane + 32;
                int col = w0 - 2 + col_l2;
                bool ok = rowok && (col >= 0) && (col < WIN);
                float v = ok ? src[col] : 0.f;
                if (FUSED) v = ok ? fmaxf(v * sc + tc, 0.f) : 0.f;
                xsm[base + col_l2 * 4] = v;
            }
        }

        __syncthreads();

        // ---- main compute
#pragma unroll 1
        for (int cl = 0; cl < 8; ++cl) {
#pragma unroll
            for (int kh = 0; kh < 3; ++kh) {
                const float* xrow = &xsm[(((cl * 3 + kh) * 4) * 34) * 4];
#pragma unroll
                for (int kw = 0; kw < 3; ++kw) {
                    int kl = cl * 9 + kh * 3 + kw;
                    const float4* wp = (const float4*)&wsm[(kl * 64 + obase) * 4];
                    float weff[4];
#pragma unroll
                    for (int j = 0; j < 4; ++j) {
                        float4 wv = wp[j];
                        weff[j] = cw[0] * wv.x + cw[1] * wv.y + cw[2] * wv.z + cw[3] * wv.w;
                    }
#pragma unroll
                    for (int bg = 0; bg < 4; ++bg) {
                        float4 xv = *(const float4*)&xrow[(bg * 34 + tx + kw) * 4];
#pragma unroll
                        for (int j = 0; j < 4; ++j) {
                            acc[j * 16 + bg * 4 + 0] = fmaf(weff[j], xv.x, acc[j * 16 + bg * 4 + 0]);
                            acc[j * 16 + bg * 4 + 1] = fmaf(weff[j], xv.y, acc[j * 16 + bg * 4 + 1]);
                            acc[j * 16 + bg * 4 + 2] = fmaf(weff[j], xv.z, acc[j * 16 + bg * 4 + 2]);
                            acc[j * 16 + bg * 4 + 3] = fmaf(weff[j], xv.w, acc[j * 16 + bg * 4 + 3]);
                        }
                    }
                }
            }
        }
    }

    // ---- epilogue: bias, store, BN-stat accumulation
#pragma unroll
    for (int j = 0; j < 4; ++j) {
        int o = obase + j;
        float bia = bias[o];
        float s0 = 0.f, s1 = 0.f;
#pragma unroll
        for (int b = 0; b < 16; ++b) {
            float v = acc[j * 16 + b] + bia;
            if (wvalid)
                yout[((size_t)(b * COUT + o) * HO + h) * WO + wq] = v;
            float vs = wvalid ? v : 0.f;
            s0 += vs;
            s1 += vs * vs;
        }
#pragma unroll
        for (int off = 16; off > 0; off >>= 1) {
            s0 += __shfl_xor_sync(0xffffffffu, s0, off);
            s1 += __shfl_xor_sync(0xffffffffu, s1, off);
        }
        if (lane == 0) {
            atomicAdd(&stats[o], s0);
            atomicAdd(&stats[COUT + o], s1);
        }
    }
}

// BN + ReLU + 3x3/3 maxpool (all candidates >= 0 after relu, so init 0 is exact)
__global__ void bn_relu_pool_kernel(const float* __restrict__ h2,
                                    const float* __restrict__ st,
                                    float* __restrict__ out) {
    int idx = blockIdx.x * blockDim.x + threadIdx.x;
    const int total = BATCH * COUT * POH * POW;
    if (idx >= total) return;
    int ow = idx % POW;
    int t  = idx / POW;
    int oh = t % POH;  t /= POH;
    int c  = t % COUT;
    int b  = t / COUT;
    float s  = st[c];
    float tt = st[COUT + c];
    const float* p = h2 + ((size_t)(b * COUT + c) * HO2 + oh * 3) * WO2 + ow * 3;
    float v = 0.f;
#pragma unroll
    for (int kh = 0; kh < 3; ++kh)
#pragma unroll
        for (int kw = 0; kw < 3; ++kw) {
            float u = fmaxf(p[kh * WO2 + kw] * s + tt, 0.f);
            v = fmaxf(v, u);
        }
    out[idx] = v;
}

extern "C" void kernel_launch(void* const* d_in, const int* in_sizes, int n_in,
                              void* d_out, int out_size) {
    const float* x   = (const float*)d_in[0];
    const float* w1  = (const float*)d_in[1];
    const float* b1  = (const float*)d_in[2];
    const float* a1h = (const float*)d_in[3];
    const float* a1w = (const float*)d_in[4];
    const float* g1  = (const float*)d_in[5];
    const float* be1 = (const float*)d_in[6];
    const float* w2  = (const float*)d_in[7];
    const float* b2  = (const float*)d_in[8];
    const float* a2h = (const float*)d_in[9];
    const float* a2w = (const float*)d_in[10];
    const float* g2  = (const float*)d_in[11];
    const float* be2 = (const float*)d_in[12];

    float *h1, *h2, *stats, *st;
    cudaGetSymbolAddress((void**)&h1, g_h1);
    cudaGetSymbolAddress((void**)&h2, g_h2);
    cudaGetSymbolAddress((void**)&stats, g_stats);
    cudaGetSymbolAddress((void**)&st, g_st);

    const size_t smem = (size_t)(72 * 64 * 4 + 8 * 3 * 4 * 34 * 4) * sizeof(float); // 125,952 B
    cudaFuncSetAttribute(lrlc_conv_kernel<32, 128, 256, 130, 258, false>,
                         cudaFuncAttributeMaxDynamicSharedMemorySize, (int)smem);
    cudaFuncSetAttribute(lrlc_conv_kernel<64, 130, 258, 132, 260, true>,
                         cudaFuncAttributeMaxDynamicSharedMemorySize, (int)smem);

    zero_stats_kernel<<<1, 256>>>();

    dim3 blk(32, 16);
    // layer 1: 258 cols -> 9 tiles of 32
    lrlc_conv_kernel<32, 128, 256, 130, 258, false>
        <<<dim3(9, 130), blk, smem>>>(x, w1, b1, a1h, a1w, nullptr, h1, stats);
    finalize_stats_kernel<<<1, 64>>>(stats, g1, be1, st, (float)(BATCH * 130 * 258));

    // layer 2: 260 cols -> 9 tiles (input BN+ReLU fused during staging)
    lrlc_conv_kernel<64, 130, 258, 132, 260, true>
        <<<dim3(9, 132), blk, smem>>>(h1, w2, b2, a2h, a2w, st, h2, stats + 128);
    finalize_stats_kernel<<<1, 64>>>(stats + 128, g2, be2, st + 128, (float)(BATCH * 132 * 260));

    const int total = BATCH * COUT * POH * POW;
    bn_relu_pool_kernel<<<(total + 255) / 256, 256>>>(h2, st + 128, (float*)d_out);
}

// round 3
// speedup vs baseline: 1.0618x; 1.0590x over previous
#include <cuda_runtime.h>
#include <math.h>

#define BATCH 16
#define COUT 64
#define RANK 4
#define EPSBN 1e-5f

// layer geometry
#define H1IN 128
#define W1IN 256
#define HO1  130
#define WO1  258
#define HO2  132
#define WO2  260
#define POH  44
#define POW  86

// scratch (static device arrays — no allocations allowed)
__device__ float g_h1[(size_t)BATCH * COUT * HO1 * WO1];   // ~137 MB
__device__ float g_h2[(size_t)BATCH * COUT * HO2 * WO2];   // ~140 MB
__device__ float g_stats[4 * COUT];                        // sum1,sq1,sum2,sq2
__device__ float g_st[4 * COUT];                           // s1,t1,s2,t2

// ---- packed f32x2 helpers (sm_103a FFMA2 path; only reachable via PTX) ----
__device__ __forceinline__ unsigned long long pk2(float v) {
    unsigned long long d; unsigned u = __float_as_uint(v);
    asm("mov.b64 %0, {%1,%1};" : "=l"(d) : "r"(u));
    return d;
}
__device__ __forceinline__ unsigned long long fma2(unsigned long long a,
                                                   unsigned long long b,
                                                   unsigned long long c) {
    unsigned long long d;
    asm("fma.rn.f32x2 %0, %1, %2, %3;" : "=l"(d) : "l"(a), "l"(b), "l"(c));
    return d;
}
__device__ __forceinline__ unsigned long long mul2(unsigned long long a,
                                                   unsigned long long b) {
    unsigned long long d;
    asm("mul.rn.f32x2 %0, %1, %2;" : "=l"(d) : "l"(a), "l"(b));
    return d;
}
// split packed (w0,w1) into broadcast pairs (w0,w0) and (w1,w1)
__device__ __forceinline__ void dup2(unsigned long long v,
                                     unsigned long long& d0,
                                     unsigned long long& d1) {
    unsigned lo, hi;
    asm("mov.b64 {%0,%1}, %2;" : "=r"(lo), "=r"(hi) : "l"(v));
    asm("mov.b64 %0, {%1,%1};" : "=l"(d0) : "r"(lo));
    asm("mov.b64 %0, {%1,%1};" : "=l"(d1) : "r"(hi));
}
__device__ __forceinline__ float2 unpk(unsigned long long v) {
    unsigned lo, hi;
    asm("mov.b64 {%0,%1}, %2;" : "=r"(lo), "=r"(hi) : "l"(v));
    float2 f; f.x = __uint_as_float(lo); f.y = __uint_as_float(hi);
    return f;
}

__global__ void zero_stats_kernel() {
    int i = threadIdx.x;
    if (i < 4 * COUT) g_stats[i] = 0.f;
}

// Per-channel BN scale/shift from accumulated sums.
__global__ void finalize_stats_kernel(const float* __restrict__ sums,
                                      const float* __restrict__ gam,
                                      const float* __restrict__ bet,
                                      float* __restrict__ st, float N) {
    int c = threadIdx.x;
    if (c < COUT) {
        float mean = sums[c] / N;
        float var  = sums[COUT + c] / N - mean * mean;
        float s    = gam[c] * rsqrtf(var + EPSBN);
        st[c]         = s;
        st[COUT + c]  = bet[c] - mean * s;
    }
}

// LRLC conv with cw-folded weights, f32x2 packed math over batch pairs.
// One CTA: one output row h, 32 output cols, all 64 out channels, all 16 batch.
// Thread (tx, og): pixel (h, w0+tx), channels og*4..og*4+3, all 16 batch
//   -> 32 packed accumulators (64 fp32).
// wsm layout: [kl(72)][r(4)][o(64)]  (channel-contiguous -> conflict-free STS,
//   4-channel float4 broadcast loads per rank in the fold)
template<int CIN, int HIN, int WIN, int HO, int WO, bool FUSED>
__global__ __launch_bounds__(512, 1)
void lrlc_conv_kernel(const float* __restrict__ xin,
                      const float* __restrict__ wgt,   // [r][o][ci][3][3]
                      const float* __restrict__ bias,
                      const float* __restrict__ ah,    // [r][HO]
                      const float* __restrict__ aw,    // [r][WO]
                      const float* __restrict__ st,    // s[64],t[64] (FUSED only)
                      float* __restrict__ yout,        // [b][o][HO][WO]
                      float* __restrict__ stats)       // sum[64], sumsq[64]
{
    extern __shared__ float sm[];
    float* wsm = sm;                    // [72][4][64] = 18432 floats
    float* xsm = sm + 72 * 256;         // [8 cl][3 kh][4 bg][34 col][4 b4] = 13056 floats

    const int tx   = threadIdx.x;       // 0..31  (w lane)
    const int og   = threadIdx.y;       // 0..15  (channel group)
    const int tid  = og * 32 + tx;
    const int lane = tx;
    const int wid  = og;

    const int h  = blockIdx.y;
    const int w0 = blockIdx.x * 32;
    const int wq = w0 + tx;
    const bool wvalid = (wq < WO);
    const int wc = wvalid ? wq : (WO - 1);

    // combining weights (softmax over rank), packed for f32x2 fold
    float lg[RANK];
#pragma unroll
    for (int r = 0; r < RANK; ++r)
        lg[r] = ah[r * HO + h] + aw[r * WO + wc];
    float mx = fmaxf(fmaxf(lg[0], lg[1]), fmaxf(lg[2], lg[3]));
    float cw[RANK];
    float esum = 0.f;
#pragma unroll
    for (int r = 0; r < RANK; ++r) { cw[r] = expf(lg[r] - mx); esum += cw[r]; }
    float einv = 1.f / esum;
    unsigned long long cwp[RANK];
#pragma unroll
    for (int r = 0; r < RANK; ++r) cwp[r] = pk2(cw[r] * einv);

    unsigned long long acc[32];         // [j(4)][bg(4)][half(2)] packed fp32 pairs
#pragma unroll
    for (int i = 0; i < 32; ++i) acc[i] = 0ull;

    const int obase = og * 4;

    for (int cc = 0; cc < CIN / 8; ++cc) {
        __syncthreads();

        // ---- stage weights: wsm[kl*256 + r*64 + o] (conflict-free STS.32)
#pragma unroll
        for (int mIt = 0; mIt < 9; ++mIt) {
            int p  = tid + mIt * 512;      // 72*64 = 4608 = 9*512
            int o  = p & 63;
            int kl = p >> 6;
#pragma unroll
            for (int r = 0; r < RANK; ++r)
                wsm[kl * 256 + r * 64 + o] =
                    wgt[(r * COUT + o) * (CIN * 9) + cc * 72 + kl];
        }

        // ---- stage x: xsm[(((cl*3+kh)*4+bg)*34+col)*4 + b4]
        for (int s = wid; s < 384; s += 16) {
            int b   = s & 15;
            int rc  = s >> 4;          // 0..23
            int cl  = rc / 3;
            int kh  = rc - cl * 3;
            int row = h - 2 + kh;
            int cin = cc * 8 + cl;
            const float* src = xin + ((size_t)(b * CIN + cin) * HIN + row) * WIN;
            float sc = 0.f, tc = 0.f;
            if (FUSED) { sc = st[cin]; tc = st[COUT + cin]; }
            int base = (((cl * 3 + kh) * 4 + (b >> 2)) * 34) * 4 + (b & 3);
            bool rowok = (row >= 0) && (row < HIN);

            {
                int col = w0 - 2 + lane;
                bool ok = rowok && (col >= 0) && (col < WIN);
                float v = ok ? src[col] : 0.f;
                if (FUSED) v = ok ? fmaxf(v * sc + tc, 0.f) : 0.f;
                xsm[base + lane * 4] = v;
            }
            if (lane < 2) {
                int col_l2 = lane + 32;
                int col = w0 - 2 + col_l2;
                bool ok = rowok && (col >= 0) && (col < WIN);
                float v = ok ? src[col] : 0.f;
                if (FUSED) v = ok ? fmaxf(v * sc + tc, 0.f) : 0.f;
                xsm[base + col_l2 * 4] = v;
            }
        }

        __syncthreads();

        // ---- main compute (packed f32x2)
#pragma unroll 1
        for (int cl = 0; cl < 8; ++cl) {
#pragma unroll
            for (int kh = 0; kh < 3; ++kh) {
                const float* xrow = &xsm[(((cl * 3 + kh) * 4) * 34) * 4];
#pragma unroll
                for (int kw = 0; kw < 3; ++kw) {
                    int kl = cl * 9 + kh * 3 + kw;
                    const int kb = kl * 256 + obase;
                    // fold: weff (2-ch pairs) = sum_r cw[r] * w[r]
                    ulonglong2 wr0 = *(const ulonglong2*)&wsm[kb];
                    ulonglong2 wr1 = *(const ulonglong2*)&wsm[kb + 64];
                    ulonglong2 wr2 = *(const ulonglong2*)&wsm[kb + 128];
                    ulonglong2 wr3 = *(const ulonglong2*)&wsm[kb + 192];
                    unsigned long long wA = mul2(cwp[0], wr0.x);
                    unsigned long long wB = mul2(cwp[0], wr0.y);
                    wA = fma2(cwp[1], wr1.x, wA);
                    wB = fma2(cwp[1], wr1.y, wB);
                    wA = fma2(cwp[2], wr2.x, wA);
                    wB = fma2(cwp[2], wr2.y, wB);
                    wA = fma2(cwp[3], wr3.x, wA);
                    wB = fma2(cwp[3], wr3.y, wB);
                    unsigned long long d0, d1, d2, d3;
                    dup2(wA, d0, d1);
                    dup2(wB, d2, d3);
#pragma unroll
                    for (int bg = 0; bg < 4; ++bg) {
                        ulonglong2 xv = *(const ulonglong2*)&xrow[(bg * 34 + tx + kw) * 4];
                        acc[0 * 8 + bg * 2 + 0] = fma2(d0, xv.x, acc[0 * 8 + bg * 2 + 0]);
                        acc[0 * 8 + bg * 2 + 1] = fma2(d0, xv.y, acc[0 * 8 + bg * 2 + 1]);
                        acc[1 * 8 + bg * 2 + 0] = fma2(d1, xv.x, acc[1 * 8 + bg * 2 + 0]);
                        acc[1 * 8 + bg * 2 + 1] = fma2(d1, xv.y, acc[1 * 8 + bg * 2 + 1]);
                        acc[2 * 8 + bg * 2 + 0] = fma2(d2, xv.x, acc[2 * 8 + bg * 2 + 0]);
                        acc[2 * 8 + bg * 2 + 1] = fma2(d2, xv.y, acc[2 * 8 + bg * 2 + 1]);
                        acc[3 * 8 + bg * 2 + 0] = fma2(d3, xv.x, acc[3 * 8 + bg * 2 + 0]);
                        acc[3 * 8 + bg * 2 + 1] = fma2(d3, xv.y, acc[3 * 8 + bg * 2 + 1]);
                    }
                }
            }
        }
    }

    // ---- epilogue: bias, store, BN-stat accumulation
#pragma unroll
    for (int j = 0; j < 4; ++j) {
        int o = obase + j;
        float bia = bias[o];
        float s0 = 0.f, s1 = 0.f;
#pragma unroll
        for (int bg = 0; bg < 4; ++bg) {
#pragma unroll
            for (int hf = 0; hf < 2; ++hf) {
                float2 vv = unpk(acc[j * 8 + bg * 2 + hf]);
                int b = bg * 4 + hf * 2;
                float v0 = vv.x + bia;
                float v1 = vv.y + bia;
                if (wvalid) {
                    yout[((size_t)((b + 0) * COUT + o) * HO + h) * WO + wq] = v0;
                    yout[((size_t)((b + 1) * COUT + o) * HO + h) * WO + wq] = v1;
                }
                float m0 = wvalid ? v0 : 0.f;
                float m1 = wvalid ? v1 : 0.f;
                s0 += m0 + m1;
                s1 += m0 * m0 + m1 * m1;
            }
        }
#pragma unroll
        for (int off = 16; off > 0; off >>= 1) {
            s0 += __shfl_xor_sync(0xffffffffu, s0, off);
            s1 += __shfl_xor_sync(0xffffffffu, s1, off);
        }
        if (lane == 0) {
            atomicAdd(&stats[o], s0);
            atomicAdd(&stats[COUT + o], s1);
        }
    }
}

// BN + ReLU + 3x3/3 maxpool (all candidates >= 0 after relu, so init 0 is exact)
__global__ void bn_relu_pool_kernel(const float* __restrict__ h2,
                                    const float* __restrict__ st,
                                    float* __restrict__ out) {
    int idx = blockIdx.x * blockDim.x + threadIdx.x;
    const int total = BATCH * COUT * POH * POW;
    if (idx >= total) return;
    int ow = idx % POW;
    int t  = idx / POW;
    int oh = t % POH;  t /= POH;
    int c  = t % COUT;
    int b  = t / COUT;
    float s  = st[c];
    float tt = st[COUT + c];
    const float* p = h2 + ((size_t)(b * COUT + c) * HO2 + oh * 3) * WO2 + ow * 3;
    float v = 0.f;
#pragma unroll
    for (int kh = 0; kh < 3; ++kh)
#pragma unroll
        for (int kw = 0; kw < 3; ++kw) {
            float u = fmaxf(p[kh * WO2 + kw] * s + tt, 0.f);
            v = fmaxf(v, u);
        }
    out[idx] = v;
}

extern "C" void kernel_launch(void* const* d_in, const int* in_sizes, int n_in,
                              void* d_out, int out_size) {
    const float* x   = (const float*)d_in[0];
    const float* w1  = (const float*)d_in[1];
    const float* b1  = (const float*)d_in[2];
    const float* a1h = (const float*)d_in[3];
    const float* a1w = (const float*)d_in[4];
    const float* g1  = (const float*)d_in[5];
    const float* be1 = (const float*)d_in[6];
    const float* w2  = (const float*)d_in[7];
    const float* b2  = (const float*)d_in[8];
    const float* a2h = (const float*)d_in[9];
    const float* a2w = (const float*)d_in[10];
    const float* g2  = (const float*)d_in[11];
    const float* be2 = (const float*)d_in[12];

    float *h1, *h2, *stats, *st;
    cudaGetSymbolAddress((void**)&h1, g_h1);
    cudaGetSymbolAddress((void**)&h2, g_h2);
    cudaGetSymbolAddress((void**)&stats, g_stats);
    cudaGetSymbolAddress((void**)&st, g_st);

    const size_t smem = (size_t)(72 * 256 + 8 * 3 * 4 * 34 * 4) * sizeof(float); // 125,952 B
    cudaFuncSetAttribute(lrlc_conv_kernel<32, 128, 256, 130, 258, false>,
                         cudaFuncAttributeMaxDynamicSharedMemorySize, (int)smem);
    cudaFuncSetAttribute(lrlc_conv_kernel<64, 130, 258, 132, 260, true>,
                         cudaFuncAttributeMaxDynamicSharedMemorySize, (int)smem);

    zero_stats_kernel<<<1, 256>>>();

    dim3 blk(32, 16);
    // layer 1: 258 cols -> 9 tiles of 32
    lrlc_conv_kernel<32, 128, 256, 130, 258, false>
        <<<dim3(9, 130), blk, smem>>>(x, w1, b1, a1h, a1w, nullptr, h1, stats);
    finalize_stats_kernel<<<1, 64>>>(stats, g1, be1, st, (float)(BATCH * 130 * 258));

    // layer 2: 260 cols -> 9 tiles (input BN+ReLU fused during staging)
    lrlc_conv_kernel<64, 130, 258, 132, 260, true>
        <<<dim3(9, 132), blk, smem>>>(h1, w2, b2, a2h, a2w, st, h2, stats + 128);
    finalize_stats_kernel<<<1, 64>>>(stats + 128, g2, be2, st + 128, (float)(BATCH * 132 * 260));

    const int total = BATCH * COUT * POH * POW;
    bn_relu_pool_kernel<<<(total + 255) / 256, 256>>>(h2, st + 128, (float*)d_out);
}